// round 12
// baseline (speedup 1.0000x reference)
#include <cuda_runtime.h>
#include <cuda_fp16.h>
#include <math.h>
#include <stdint.h>

// ---------------------------------------------------------------------------
// GaussianVectorQuantizer (train path) — HMMA fp16 2-pass split GEMMs,
// cp.async 3-stage single-sync pipeline, warp-pair fused softmax.
// ---------------------------------------------------------------------------

static constexpr int Bb = 8;
static constexpr int Cd = 256;     // BOOK_DIM
static constexpr int Tt = 4096;
static constexpr int Nn = Bb * Tt; // 32768
static constexpr int Kb = 1024;    // BOOK_SIZE

static constexpr size_t OFF_PREC = (size_t)Bb * Cd * Tt;
static constexpr size_t OFF_PROB = OFF_PREC + 1;
static constexpr size_t OFF_LOGP = OFF_PROB + (size_t)Nn * Kb;
static constexpr size_t OFF_MEAN = OFF_LOGP + (size_t)Nn * Kb;

// Scratch (device globals; no allocation allowed)
__device__ float g_zn2[Nn];
__device__ float g_ek2[Kb];
__device__ __half g_zh[(size_t)Nn * Cd];   // zf hi, [n][c]
__device__ __half g_zl[(size_t)Nn * Cd];   // zf lo
__device__ __half g_bh[Kb * Cd];           // book fp16, [k][c]
__device__ __half g_bth[Cd * Kb];          // book^T fp16, [c][k]
__device__ __half g_eh[(size_t)Nn * Kb];   // encodings hi, [n][k]
__device__ __half g_el[(size_t)Nn * Kb];   // encodings lo

// =============================== helpers ===================================
__device__ __forceinline__ uint32_t smem_u32(const void* p) {
    uint32_t a;
    asm("{ .reg .u64 t; cvta.to.shared.u64 t, %1; cvt.u32.u64 %0, t; }"
        : "=r"(a) : "l"(p));
    return a;
}
__device__ __forceinline__ void cp_async16(uint32_t saddr, const void* gptr) {
    asm volatile("cp.async.cg.shared.global [%0], [%1], 16;"
                 :: "r"(saddr), "l"(gptr));
}
__device__ __forceinline__ void cp_commit() {
    asm volatile("cp.async.commit_group;" ::: "memory");
}
template<int N> __device__ __forceinline__ void cp_wait() {
    asm volatile("cp.async.wait_group %0;" :: "n"(N) : "memory");
}
__device__ __forceinline__ void mma16816(float c[4], const uint32_t a[4],
                                         uint32_t b0, uint32_t b1) {
    asm volatile(
        "mma.sync.aligned.m16n8k16.row.col.f32.f16.f16.f32 "
        "{%0,%1,%2,%3}, {%4,%5,%6,%7}, {%8,%9}, {%0,%1,%2,%3};"
        : "+f"(c[0]), "+f"(c[1]), "+f"(c[2]), "+f"(c[3])
        : "r"(a[0]), "r"(a[1]), "r"(a[2]), "r"(a[3]), "r"(b0), "r"(b1));
}

static constexpr int LDT = 40;               // smem row stride in halves (80 B)
static constexpr int TILE_B = 128 * LDT * 2; // 10240 bytes per 128x32 tile
static constexpr int STAGE_B = 3 * TILE_B;   // 30720 bytes (Ah, Al, Bh)
static constexpr int NSTG = 3;
static constexpr int SMEM_GEMM = NSTG * STAGE_B; // 92160

// A fragment (16x16) from K-major smem tile
__device__ __forceinline__ void lda_frag(uint32_t a[4],
                                         const __half (*T)[LDT],
                                         int row, int kk, int g, int t2) {
    a[0] = *(const uint32_t*)&T[row + g][kk + t2];
    a[1] = *(const uint32_t*)&T[row + g + 8][kk + t2];
    a[2] = *(const uint32_t*)&T[row + g][kk + t2 + 8];
    a[3] = *(const uint32_t*)&T[row + g + 8][kk + t2 + 8];
}

// Async-load one 128x32 fp16 tile (K-major gmem) into smem tile at `sm`
__device__ __forceinline__ void tile_async(char* sm,
                                           const __half* __restrict__ g,
                                           int ld, int kk0, int tid) {
    #pragma unroll
    for (int i = 0; i < 2; i++) {
        int idx = tid + i * 256;
        int row = idx >> 2, c8 = (idx & 3) * 8;
        cp_async16(smem_u32(sm + row * (LDT * 2) + c8 * 2),
                   g + (size_t)row * ld + kk0 + c8);
    }
}

// Pipelined 2-pass fp16-split GEMM mainloop. NCH chunks of K=32, 3 stages,
// ONE __syncthreads per chunk: the top-of-loop barrier proves all warps
// finished compute(ch-1), so slot (ch+2)%3 == (ch-1)%3 may be refilled.
template<int NCH>
__device__ __forceinline__ void gemm_body(
    const __half* __restrict__ Agh, const __half* __restrict__ Agl,
    const __half* __restrict__ Bgh,
    int lda, int ldb, float acc[2][8][4], char* dsm, int tid,
    int g, int t2, int wm, int wn)
{
    auto issue = [&](int ch) {
        char* st = dsm + (ch % NSTG) * STAGE_B;
        int kk0 = ch * 32;
        tile_async(st + 0 * TILE_B, Agh, lda, kk0, tid);
        tile_async(st + 1 * TILE_B, Agl, lda, kk0, tid);
        tile_async(st + 2 * TILE_B, Bgh, ldb, kk0, tid);
    };
    issue(0);
    cp_commit();
    if (NCH > 1) issue(1);
    cp_commit();

    for (int ch = 0; ch < NCH; ch++) {
        cp_wait<1>();          // stage ch resident
        __syncthreads();       // all warps done with stage ch-1
        if (ch + 2 < NCH) issue(ch + 2);
        cp_commit();           // always commit: uniform group accounting
        char* st = dsm + (ch % NSTG) * STAGE_B;
        const __half (*Ah)[LDT] = (const __half (*)[LDT])(st + 0 * TILE_B);
        const __half (*Al)[LDT] = (const __half (*)[LDT])(st + 1 * TILE_B);
        const __half (*Bh)[LDT] = (const __half (*)[LDT])(st + 2 * TILE_B);
        #pragma unroll
        for (int ks = 0; ks < 2; ks++) {
            int kk = ks * 16;
            uint32_t ah[2][4], al[2][4];
            #pragma unroll
            for (int i = 0; i < 2; i++) {
                lda_frag(ah[i], Ah, wm + i * 16, kk, g, t2);
                lda_frag(al[i], Al, wm + i * 16, kk, g, t2);
            }
            #pragma unroll
            for (int j = 0; j < 8; j++) {
                int col = wn + j * 8 + g;
                uint32_t b0 = *(const uint32_t*)&Bh[col][kk + t2];
                uint32_t b1 = *(const uint32_t*)&Bh[col][kk + t2 + 8];
                #pragma unroll
                for (int i = 0; i < 2; i++) {
                    mma16816(acc[i][j], ah[i], b0, b1);
                    mma16816(acc[i][j], al[i], b0, b1);
                }
            }
        }
    }
}

// ======================= prep: norms, book fp16 ============================
__global__ void prep_kernel(const float* __restrict__ book,
                            const float* __restrict__ lpq,
                            float* __restrict__ out) {
    __shared__ float red[256];
    int k = blockIdx.x, c = threadIdx.x;
    float v = book[(size_t)k * Cd + c];
    __half h = __float2half(v);
    g_bh[(size_t)k * Cd + c] = h;
    g_bth[(size_t)c * Kb + k] = h;
    red[c] = v * v;
    __syncthreads();
    for (int s = 128; s > 0; s >>= 1) {
        if (c < s) red[c] += red[c + s];
        __syncthreads();
    }
    if (c == 0) {
        g_ek2[k] = red[0];
        out[OFF_MEAN + k] = 0.0f;
        if (k == 0) out[OFF_PREC] = 0.5f / fmaxf(1.0f + expf(lpq[0]), 1e-10f);
    }
}

// ================= z: transpose + fp16 split  [b][c][t] -> [n][c] ==========
__global__ void zsplit_kernel(const float* __restrict__ z) {
    __shared__ float sm[32][33];
    int tx = threadIdx.x, ty = threadIdx.y;
    int t0 = blockIdx.x * 32, c0 = blockIdx.y * 32, b = blockIdx.z;
    const float* zb = z + (size_t)b * Cd * Tt;
    #pragma unroll
    for (int i = 0; i < 4; i++) {
        int cl = ty + 8 * i;
        sm[cl][tx] = zb[(size_t)(c0 + cl) * Tt + t0 + tx];
    }
    __syncthreads();
    #pragma unroll
    for (int i = 0; i < 4; i++) {
        int tl = ty + 8 * i;
        float v = sm[tx][tl];
        __half hi = __float2half(v);
        __half lo = __float2half(v - __half2float(hi));
        size_t n = (size_t)b * Tt + t0 + tl;
        g_zh[n * Cd + c0 + tx] = hi;
        g_zl[n * Cd + c0 + tx] = lo;
    }
}

// =========================== z row norms ===================================
__global__ void znorm_kernel(const float* __restrict__ z) {
    int n = blockIdx.x * blockDim.x + threadIdx.x;
    int b = n >> 12, t = n & 4095;
    const float* zp = z + (size_t)b * Cd * Tt + t;
    float acc = 0.f;
    #pragma unroll 8
    for (int c = 0; c < Cd; c++) {
        float v = zp[(size_t)c * Tt];
        acc += v * v;
    }
    g_zn2[n] = acc;
}

// ================== GEMM1 (HMMA): logits = f(zf . book^T) ==================
__global__ void __launch_bounds__(256, 2) gemm1_mma(const float* __restrict__ lpq,
                                                    float* __restrict__ out) {
    extern __shared__ char dsm[];
    const int tid = threadIdx.x, wid = tid >> 5, lane = tid & 31;
    const int g = lane >> 2, t2 = (lane & 3) * 2;
    const int wm = (wid & 3) * 32, wn = (wid >> 2) * 64;
    const int k0 = blockIdx.x * 128;   // book rows
    const int m0 = blockIdx.y * 128;   // z rows

    float acc[2][8][4];
    #pragma unroll
    for (int i = 0; i < 2; i++)
        #pragma unroll
        for (int j = 0; j < 8; j++)
            #pragma unroll
            for (int q = 0; q < 4; q++) acc[i][j][q] = 0.f;

    gemm_body<Cd / 32>(g_zh + (size_t)m0 * Cd, g_zl + (size_t)m0 * Cd,
                       g_bh + (size_t)k0 * Cd,
                       Cd, Cd, acc, dsm, tid, g, t2, wm, wn);

    float prec = 0.5f / fmaxf(1.0f + expf(lpq[0]), 1e-10f);
    float* L = out + OFF_PROB;
    #pragma unroll
    for (int i = 0; i < 2; i++) {
        int r0 = m0 + wm + i * 16 + g;
        float zn0 = g_zn2[r0], zn1 = g_zn2[r0 + 8];
        #pragma unroll
        for (int j = 0; j < 8; j++) {
            int c = k0 + wn + j * 8 + t2;
            float ek0 = g_ek2[c], ek1 = g_ek2[c + 1];
            L[(size_t)r0 * Kb + c]           = (2.f * acc[i][j][0] - zn0 - ek0) * prec;
            L[(size_t)r0 * Kb + c + 1]       = (2.f * acc[i][j][1] - zn0 - ek1) * prec;
            L[(size_t)(r0 + 8) * Kb + c]     = (2.f * acc[i][j][2] - zn1 - ek0) * prec;
            L[(size_t)(r0 + 8) * Kb + c + 1] = (2.f * acc[i][j][3] - zn1 - ek1) * prec;
        }
    }
}

// ===== Fused softmax, warp-pair per row: prob/log_prob/mean + Gumbel enc ===
// 8 warps = 4 pairs; pair p handles row rr*4+p, warp half h covers 512 cols.
// Cross-warp reductions via rotating smem slots, one __syncthreads per phase.
__global__ void __launch_bounds__(256) softmax_fused(const float* __restrict__ u,
                                                     float* __restrict__ out) {
    __shared__ float redA[8], redB[8], redC[8], redD[8];
    __shared__ float msum[1024];
    const int tid = threadIdx.x, lane = tid & 31, w = tid >> 5;
    const int p = w >> 1, h = w & 1;
    for (int i = tid; i < 1024; i += 256) msum[i] = 0.f;
    float macc[16];
    #pragma unroll
    for (int i = 0; i < 16; i++) macc[i] = 0.f;
    __syncthreads();

    for (int rr = 0; rr < 8; rr++) {
        int n = blockIdx.x * 32 + rr * 4 + p;
        float* Lrow = out + OFF_PROB + (size_t)n * Kb + h * 512;
        float* LPr  = out + OFF_LOGP + (size_t)n * Kb + h * 512;
        const float* urow = u + (size_t)n * Kb + h * 512;

        float x[16];
        float mx = -1e30f;
        #pragma unroll
        for (int i = 0; i < 16; i++) {
            x[i] = Lrow[i * 32 + lane];
            mx = fmaxf(mx, x[i]);
        }
        #pragma unroll
        for (int o = 16; o > 0; o >>= 1)
            mx = fmaxf(mx, __shfl_xor_sync(0xffffffffu, mx, o));
        if (lane == 0) redA[w] = mx;
        __syncthreads();
        mx = fmaxf(redA[p * 2], redA[p * 2 + 1]);

        float s = 0.f;
        #pragma unroll
        for (int i = 0; i < 16; i++) s += __expf(x[i] - mx);
        #pragma unroll
        for (int o = 16; o > 0; o >>= 1)
            s += __shfl_xor_sync(0xffffffffu, s, o);
        if (lane == 0) redB[w] = s;
        __syncthreads();
        s = redB[p * 2] + redB[p * 2 + 1];

        float inv = 1.f / s;
        float lZ  = logf(s);
        #pragma unroll
        for (int i = 0; i < 16; i++) {
            float pr = __expf(x[i] - mx) * inv;
            Lrow[i * 32 + lane] = pr;                  // prob (in-place)
            LPr[i * 32 + lane]  = x[i] - mx - lZ;      // log_prob
            macc[i] += pr;
        }

        // Gumbel-softmax encodings; overwrite x with scaled logits
        float mx2 = -1e30f;
        #pragma unroll
        for (int i = 0; i < 16; i++) {
            float uu = urow[i * 32 + lane];
            float gmb = -logf(-logf(uu + 1e-10f) + 1e-10f);
            x[i] = (x[i] + gmb) * 2.0f;   // / TEMPERATURE(0.5)
            mx2 = fmaxf(mx2, x[i]);
        }
        #pragma unroll
        for (int o = 16; o > 0; o >>= 1)
            mx2 = fmaxf(mx2, __shfl_xor_sync(0xffffffffu, mx2, o));
        if (lane == 0) redC[w] = mx2;
        __syncthreads();
        mx2 = fmaxf(redC[p * 2], redC[p * 2 + 1]);

        float s2 = 0.f;
        #pragma unroll
        for (int i = 0; i < 16; i++) s2 += __expf(x[i] - mx2);
        #pragma unroll
        for (int o = 16; o > 0; o >>= 1)
            s2 += __shfl_xor_sync(0xffffffffu, s2, o);
        if (lane == 0) redD[w] = s2;
        __syncthreads();
        s2 = redD[p * 2] + redD[p * 2 + 1];

        float inv2 = 1.f / s2;
        __half* Eh = g_eh + (size_t)n * Kb + h * 512;
        __half* El = g_el + (size_t)n * Kb + h * 512;
        #pragma unroll
        for (int i = 0; i < 16; i++) {
            float e = __expf(x[i] - mx2) * inv2;
            __half hi = __float2half(e);
            Eh[i * 32 + lane] = hi;
            El[i * 32 + lane] = __float2half(e - __half2float(hi));
        }
    }

    #pragma unroll
    for (int i = 0; i < 16; i++)
        atomicAdd(&msum[h * 512 + i * 32 + lane], macc[i]);
    __syncthreads();
    const float invN = 1.0f / (float)Nn;
    for (int idx = tid; idx < 1024; idx += 256)
        atomicAdd(&out[OFF_MEAN + idx], msum[idx] * invN);
}

// ================= GEMM2 (HMMA): z_q = enc . book, -> [B,C,T] ==============
__global__ void __launch_bounds__(256, 2) gemm2_mma(float* __restrict__ out) {
    extern __shared__ char dsm[];
    const int tid = threadIdx.x, wid = tid >> 5, lane = tid & 31;
    const int g = lane >> 2, t2 = (lane & 3) * 2;
    const int wm = (wid & 3) * 32, wn = (wid >> 2) * 64;
    const int c0 = blockIdx.x * 128;   // output channel
    const int m0 = blockIdx.y * 128;   // row (n)

    float acc[2][8][4];
    #pragma unroll
    for (int i = 0; i < 2; i++)
        #pragma unroll
        for (int j = 0; j < 8; j++)
            #pragma unroll
            for (int q = 0; q < 4; q++) acc[i][j][q] = 0.f;

    gemm_body<Kb / 32>(g_eh + (size_t)m0 * Kb, g_el + (size_t)m0 * Kb,
                       g_bth + (size_t)c0 * Kb,
                       Kb, Kb, acc, dsm, tid, g, t2, wm, wn);

    int b = m0 >> 12, t0 = m0 & 4095;
    float* Ob = out + (size_t)b * Cd * Tt;
    #pragma unroll
    for (int i = 0; i < 2; i++) {
        int tp = t0 + wm + i * 16 + g;
        #pragma unroll
        for (int j = 0; j < 8; j++) {
            int c = c0 + wn + j * 8 + t2;
            Ob[(size_t)c * Tt + tp]           = acc[i][j][0];
            Ob[(size_t)(c + 1) * Tt + tp]     = acc[i][j][1];
            Ob[(size_t)c * Tt + tp + 8]       = acc[i][j][2];
            Ob[(size_t)(c + 1) * Tt + tp + 8] = acc[i][j][3];
        }
    }
}

// ---------------------------------------------------------------------------
extern "C" void kernel_launch(void* const* d_in, const int* in_sizes, int n_in,
                              void* d_out, int out_size) {
    const float* z    = (const float*)d_in[0];
    const float* book = (const float*)d_in[1];
    const float* lpq  = (const float*)d_in[2];
    const float* u    = (const float*)d_in[3];
    float* out = (float*)d_out;

    cudaFuncSetAttribute(gemm1_mma, cudaFuncAttributeMaxDynamicSharedMemorySize, SMEM_GEMM);
    cudaFuncSetAttribute(gemm2_mma, cudaFuncAttributeMaxDynamicSharedMemorySize, SMEM_GEMM);

    prep_kernel<<<Kb, 256>>>(book, lpq, out);
    zsplit_kernel<<<dim3(Tt / 32, Cd / 32, Bb), dim3(32, 8)>>>(z);
    znorm_kernel<<<Nn / 256, 256>>>(z);
    gemm1_mma<<<dim3(Kb / 128, Nn / 128), 256, SMEM_GEMM>>>(lpq, out);
    softmax_fused<<<Nn / 32, 256>>>(u, out);
    gemm2_mma<<<dim3(Cd / 128, Nn / 128), 256, SMEM_GEMM>>>(out);
}

// round 14
// speedup vs baseline: 1.4739x; 1.4739x over previous
#include <cuda_runtime.h>
#include <cuda_fp16.h>
#include <math.h>
#include <stdint.h>

// ---------------------------------------------------------------------------
// GaussianVectorQuantizer (train path) — HMMA pure-fp16 1-pass GEMMs,
// cp.async 4-stage single-sync pipeline, fused softmax (R11 shape).
// Error model: fp16 rounding on both operands -> ~4.5e-4 logit error,
// gate is 1e-3 (R11 measured 3.16e-4 with one-sided error).
// (Resubmission of R13 source — previous round died on container infra,
// no kernel-level evidence was produced.)
// ---------------------------------------------------------------------------

static constexpr int Bb = 8;
static constexpr int Cd = 256;     // BOOK_DIM
static constexpr int Tt = 4096;
static constexpr int Nn = Bb * Tt; // 32768
static constexpr int Kb = 1024;    // BOOK_SIZE

static constexpr size_t OFF_PREC = (size_t)Bb * Cd * Tt;
static constexpr size_t OFF_PROB = OFF_PREC + 1;
static constexpr size_t OFF_LOGP = OFF_PROB + (size_t)Nn * Kb;
static constexpr size_t OFF_MEAN = OFF_LOGP + (size_t)Nn * Kb;

// Scratch (device globals; no allocation allowed)
__device__ float g_zn2[Nn];
__device__ float g_ek2[Kb];
__device__ __half g_zh[(size_t)Nn * Cd];   // zf fp16, [n][c]
__device__ __half g_bh[Kb * Cd];           // book fp16, [k][c]
__device__ __half g_bth[Cd * Kb];          // book^T fp16, [c][k]
__device__ __half g_eh[(size_t)Nn * Kb];   // encodings fp16, [n][k]

// =============================== helpers ===================================
__device__ __forceinline__ uint32_t smem_u32(const void* p) {
    uint32_t a;
    asm("{ .reg .u64 t; cvta.to.shared.u64 t, %1; cvt.u32.u64 %0, t; }"
        : "=r"(a) : "l"(p));
    return a;
}
__device__ __forceinline__ void cp_async16(uint32_t saddr, const void* gptr) {
    asm volatile("cp.async.cg.shared.global [%0], [%1], 16;"
                 :: "r"(saddr), "l"(gptr));
}
__device__ __forceinline__ void cp_commit() {
    asm volatile("cp.async.commit_group;" ::: "memory");
}
template<int N> __device__ __forceinline__ void cp_wait() {
    asm volatile("cp.async.wait_group %0;" :: "n"(N) : "memory");
}
__device__ __forceinline__ void mma16816(float c[4], const uint32_t a[4],
                                         uint32_t b0, uint32_t b1) {
    asm volatile(
        "mma.sync.aligned.m16n8k16.row.col.f32.f16.f16.f32 "
        "{%0,%1,%2,%3}, {%4,%5,%6,%7}, {%8,%9}, {%0,%1,%2,%3};"
        : "+f"(c[0]), "+f"(c[1]), "+f"(c[2]), "+f"(c[3])
        : "r"(a[0]), "r"(a[1]), "r"(a[2]), "r"(a[3]), "r"(b0), "r"(b1));
}

static constexpr int LDT = 40;               // smem row stride in halves (80 B)
static constexpr int TILE_B = 128 * LDT * 2; // 10240 bytes per 128x32 tile
static constexpr int STAGE_B = 2 * TILE_B;   // 20480 bytes (A, B)
static constexpr int NSTG = 4;
static constexpr int SMEM_GEMM = NSTG * STAGE_B; // 81920

// A fragment (16x16) from K-major smem tile
__device__ __forceinline__ void lda_frag(uint32_t a[4],
                                         const __half (*T)[LDT],
                                         int row, int kk, int g, int t2) {
    a[0] = *(const uint32_t*)&T[row + g][kk + t2];
    a[1] = *(const uint32_t*)&T[row + g + 8][kk + t2];
    a[2] = *(const uint32_t*)&T[row + g][kk + t2 + 8];
    a[3] = *(const uint32_t*)&T[row + g + 8][kk + t2 + 8];
}

// Async-load one 128x32 fp16 tile (K-major gmem) into smem tile at `sm`
__device__ __forceinline__ void tile_async(char* sm,
                                           const __half* __restrict__ g,
                                           int ld, int kk0, int tid) {
    #pragma unroll
    for (int i = 0; i < 2; i++) {
        int idx = tid + i * 256;
        int row = idx >> 2, c8 = (idx & 3) * 8;
        cp_async16(smem_u32(sm + row * (LDT * 2) + c8 * 2),
                   g + (size_t)row * ld + kk0 + c8);
    }
}

// Pipelined 1-pass fp16 GEMM mainloop. NCH chunks of K=32, 4 stages,
// one __syncthreads per chunk (slot (ch+3)%4 == (ch-1)%4, proven free
// by the top-of-loop barrier).
template<int NCH>
__device__ __forceinline__ void gemm_body(
    const __half* __restrict__ Ag, const __half* __restrict__ Bg,
    int lda, int ldb, float acc[2][8][4], char* dsm, int tid,
    int g, int t2, int wm, int wn)
{
    auto issue = [&](int ch) {
        char* st = dsm + (ch % NSTG) * STAGE_B;
        int kk0 = ch * 32;
        tile_async(st + 0 * TILE_B, Ag, lda, kk0, tid);
        tile_async(st + 1 * TILE_B, Bg, ldb, kk0, tid);
    };
    issue(0);
    cp_commit();
    if (NCH > 1) issue(1);
    cp_commit();
    if (NCH > 2) issue(2);
    cp_commit();

    for (int ch = 0; ch < NCH; ch++) {
        cp_wait<2>();          // stage ch resident
        __syncthreads();       // all warps done with stage ch-1
        if (ch + 3 < NCH) issue(ch + 3);
        cp_commit();           // always commit: uniform group accounting
        char* st = dsm + (ch % NSTG) * STAGE_B;
        const __half (*Ah)[LDT] = (const __half (*)[LDT])(st + 0 * TILE_B);
        const __half (*Bh)[LDT] = (const __half (*)[LDT])(st + 1 * TILE_B);
        #pragma unroll
        for (int ks = 0; ks < 2; ks++) {
            int kk = ks * 16;
            uint32_t ah[2][4];
            #pragma unroll
            for (int i = 0; i < 2; i++)
                lda_frag(ah[i], Ah, wm + i * 16, kk, g, t2);
            #pragma unroll
            for (int j = 0; j < 8; j++) {
                int col = wn + j * 8 + g;
                uint32_t b0 = *(const uint32_t*)&Bh[col][kk + t2];
                uint32_t b1 = *(const uint32_t*)&Bh[col][kk + t2 + 8];
                #pragma unroll
                for (int i = 0; i < 2; i++)
                    mma16816(acc[i][j], ah[i], b0, b1);
            }
        }
    }
}

// ======================= prep: norms, book fp16 ============================
__global__ void prep_kernel(const float* __restrict__ book,
                            const float* __restrict__ lpq,
                            float* __restrict__ out) {
    __shared__ float red[256];
    int k = blockIdx.x, c = threadIdx.x;
    float v = book[(size_t)k * Cd + c];
    __half h = __float2half(v);
    g_bh[(size_t)k * Cd + c] = h;
    g_bth[(size_t)c * Kb + k] = h;
    red[c] = v * v;
    __syncthreads();
    for (int s = 128; s > 0; s >>= 1) {
        if (c < s) red[c] += red[c + s];
        __syncthreads();
    }
    if (c == 0) {
        g_ek2[k] = red[0];
        out[OFF_MEAN + k] = 0.0f;
        if (k == 0) out[OFF_PREC] = 0.5f / fmaxf(1.0f + expf(lpq[0]), 1e-10f);
    }
}

// ================= z: transpose + fp16 convert [b][c][t] -> [n][c] =========
__global__ void zsplit_kernel(const float* __restrict__ z) {
    __shared__ float sm[32][33];
    int tx = threadIdx.x, ty = threadIdx.y;
    int t0 = blockIdx.x * 32, c0 = blockIdx.y * 32, b = blockIdx.z;
    const float* zb = z + (size_t)b * Cd * Tt;
    #pragma unroll
    for (int i = 0; i < 4; i++) {
        int cl = ty + 8 * i;
        sm[cl][tx] = zb[(size_t)(c0 + cl) * Tt + t0 + tx];
    }
    __syncthreads();
    #pragma unroll
    for (int i = 0; i < 4; i++) {
        int tl = ty + 8 * i;
        float v = sm[tx][tl];
        size_t n = (size_t)b * Tt + t0 + tl;
        g_zh[n * Cd + c0 + tx] = __float2half(v);
    }
}

// =========================== z row norms ===================================
__global__ void znorm_kernel(const float* __restrict__ z) {
    int n = blockIdx.x * blockDim.x + threadIdx.x;
    int b = n >> 12, t = n & 4095;
    const float* zp = z + (size_t)b * Cd * Tt + t;
    float acc = 0.f;
    #pragma unroll 8
    for (int c = 0; c < Cd; c++) {
        float v = zp[(size_t)c * Tt];
        acc += v * v;
    }
    g_zn2[n] = acc;
}

// ================== GEMM1 (HMMA): logits = f(zf . book^T) ==================
__global__ void __launch_bounds__(256, 2) gemm1_mma(const float* __restrict__ lpq,
                                                    float* __restrict__ out) {
    extern __shared__ char dsm[];
    const int tid = threadIdx.x, wid = tid >> 5, lane = tid & 31;
    const int g = lane >> 2, t2 = (lane & 3) * 2;
    const int wm = (wid & 3) * 32, wn = (wid >> 2) * 64;
    const int k0 = blockIdx.x * 128;   // book rows
    const int m0 = blockIdx.y * 128;   // z rows

    float acc[2][8][4];
    #pragma unroll
    for (int i = 0; i < 2; i++)
        #pragma unroll
        for (int j = 0; j < 8; j++)
            #pragma unroll
            for (int q = 0; q < 4; q++) acc[i][j][q] = 0.f;

    gemm_body<Cd / 32>(g_zh + (size_t)m0 * Cd, g_bh + (size_t)k0 * Cd,
                       Cd, Cd, acc, dsm, tid, g, t2, wm, wn);

    float prec = 0.5f / fmaxf(1.0f + expf(lpq[0]), 1e-10f);
    float* L = out + OFF_PROB;
    #pragma unroll
    for (int i = 0; i < 2; i++) {
        int r0 = m0 + wm + i * 16 + g;
        float zn0 = g_zn2[r0], zn1 = g_zn2[r0 + 8];
        #pragma unroll
        for (int j = 0; j < 8; j++) {
            int c = k0 + wn + j * 8 + t2;
            float ek0 = g_ek2[c], ek1 = g_ek2[c + 1];
            L[(size_t)r0 * Kb + c]           = (2.f * acc[i][j][0] - zn0 - ek0) * prec;
            L[(size_t)r0 * Kb + c + 1]       = (2.f * acc[i][j][1] - zn0 - ek1) * prec;
            L[(size_t)(r0 + 8) * Kb + c]     = (2.f * acc[i][j][2] - zn1 - ek0) * prec;
            L[(size_t)(r0 + 8) * Kb + c + 1] = (2.f * acc[i][j][3] - zn1 - ek1) * prec;
        }
    }
}

// ===== Fused softmax: prob/log_prob/mean (pass 1) + Gumbel enc (pass 2) ====
__global__ void __launch_bounds__(256) softmax_fused(const float* __restrict__ u,
                                                     float* __restrict__ out) {
    __shared__ float sm[8 * Kb];   // per-warp mean accumulators
    int tid = threadIdx.x, lane = tid & 31, w = tid >> 5;
    for (int i = tid; i < 8 * Kb; i += 256) sm[i] = 0.f;
    __syncthreads();

    for (int rr = 0; rr < 4; rr++) {
        int n = blockIdx.x * 32 + w * 4 + rr;
        float* Lrow = out + OFF_PROB + (size_t)n * Kb;
        float* LPr  = out + OFF_LOGP + (size_t)n * Kb;
        const float* urow = u + (size_t)n * Kb;

        float x[32];
        float mx = -1e30f;
        #pragma unroll
        for (int i = 0; i < 32; i++) {
            x[i] = Lrow[i * 32 + lane];
            mx = fmaxf(mx, x[i]);
        }
        #pragma unroll
        for (int o = 16; o > 0; o >>= 1)
            mx = fmaxf(mx, __shfl_xor_sync(0xffffffffu, mx, o));
        float s = 0.f;
        #pragma unroll
        for (int i = 0; i < 32; i++) s += __expf(x[i] - mx);
        #pragma unroll
        for (int o = 16; o > 0; o >>= 1)
            s += __shfl_xor_sync(0xffffffffu, s, o);
        float inv = 1.f / s;
        float lZ  = logf(s);
        #pragma unroll
        for (int i = 0; i < 32; i++) {
            float pr = __expf(x[i] - mx) * inv;
            Lrow[i * 32 + lane] = pr;                  // prob (in-place)
            LPr[i * 32 + lane]  = x[i] - mx - lZ;      // log_prob
            sm[w * Kb + i * 32 + lane] += pr;
        }

        // Pass 2: Gumbel-softmax encodings; overwrite x with scaled logits
        float mx2 = -1e30f;
        #pragma unroll
        for (int i = 0; i < 32; i++) {
            float uu = urow[i * 32 + lane];
            float gmb = -logf(-logf(uu + 1e-10f) + 1e-10f);
            x[i] = (x[i] + gmb) * 2.0f;   // / TEMPERATURE(0.5)
            mx2 = fmaxf(mx2, x[i]);
        }
        #pragma unroll
        for (int o = 16; o > 0; o >>= 1)
            mx2 = fmaxf(mx2, __shfl_xor_sync(0xffffffffu, mx2, o));
        float s2 = 0.f;
        #pragma unroll
        for (int i = 0; i < 32; i++) s2 += __expf(x[i] - mx2);
        #pragma unroll
        for (int o = 16; o > 0; o >>= 1)
            s2 += __shfl_xor_sync(0xffffffffu, s2, o);
        float inv2 = 1.f / s2;
        __half* Eh = g_eh + (size_t)n * Kb;
        #pragma unroll
        for (int i = 0; i < 32; i++) {
            float e = __expf(x[i] - mx2) * inv2;
            Eh[i * 32 + lane] = __float2half(e);
        }
    }

    __syncthreads();
    const float invN = 1.0f / (float)Nn;
    int k = tid * 4;
    #pragma unroll
    for (int j = 0; j < 4; j++) {
        float s = 0.f;
        #pragma unroll
        for (int ww = 0; ww < 8; ww++) s += sm[ww * Kb + k + j];
        atomicAdd(&out[OFF_MEAN + k + j], s * invN);
    }
}

// ================= GEMM2 (HMMA): z_q = enc . book, -> [B,C,T] ==============
__global__ void __launch_bounds__(256, 2) gemm2_mma(float* __restrict__ out) {
    extern __shared__ char dsm[];
    const int tid = threadIdx.x, wid = tid >> 5, lane = tid & 31;
    const int g = lane >> 2, t2 = (lane & 3) * 2;
    const int wm = (wid & 3) * 32, wn = (wid >> 2) * 64;
    const int c0 = blockIdx.x * 128;   // output channel
    const int m0 = blockIdx.y * 128;   // row (n)

    float acc[2][8][4];
    #pragma unroll
    for (int i = 0; i < 2; i++)
        #pragma unroll
        for (int j = 0; j < 8; j++)
            #pragma unroll
            for (int q = 0; q < 4; q++) acc[i][j][q] = 0.f;

    gemm_body<Kb / 32>(g_eh + (size_t)m0 * Kb, g_bth + (size_t)c0 * Kb,
                       Kb, Kb, acc, dsm, tid, g, t2, wm, wn);

    int b = m0 >> 12, t0 = m0 & 4095;
    float* Ob = out + (size_t)b * Cd * Tt;
    #pragma unroll
    for (int i = 0; i < 2; i++) {
        int tp = t0 + wm + i * 16 + g;
        #pragma unroll
        for (int j = 0; j < 8; j++) {
            int c = c0 + wn + j * 8 + t2;
            Ob[(size_t)c * Tt + tp]           = acc[i][j][0];
            Ob[(size_t)(c + 1) * Tt + tp]     = acc[i][j][1];
            Ob[(size_t)c * Tt + tp + 8]       = acc[i][j][2];
            Ob[(size_t)(c + 1) * Tt + tp + 8] = acc[i][j][3];
        }
    }
}

// ---------------------------------------------------------------------------
extern "C" void kernel_launch(void* const* d_in, const int* in_sizes, int n_in,
                              void* d_out, int out_size) {
    const float* z    = (const float*)d_in[0];
    const float* book = (const float*)d_in[1];
    const float* lpq  = (const float*)d_in[2];
    const float* u    = (const float*)d_in[3];
    float* out = (float*)d_out;

    cudaFuncSetAttribute(gemm1_mma, cudaFuncAttributeMaxDynamicSharedMemorySize, SMEM_GEMM);
    cudaFuncSetAttribute(gemm2_mma, cudaFuncAttributeMaxDynamicSharedMemorySize, SMEM_GEMM);

    prep_kernel<<<Kb, 256>>>(book, lpq, out);
    zsplit_kernel<<<dim3(Tt / 32, Cd / 32, Bb), dim3(32, 8)>>>(z);
    znorm_kernel<<<Nn / 256, 256>>>(z);
    gemm1_mma<<<dim3(Kb / 128, Nn / 128), 256, SMEM_GEMM>>>(lpq, out);
    softmax_fused<<<Nn / 32, 256>>>(u, out);
    gemm2_mma<<<dim3(Cd / 128, Nn / 128), 256, SMEM_GEMM>>>(out);
}